// round 15
// baseline (speedup 1.0000x reference)
#include <cuda_runtime.h>
#include <cstdint>

typedef unsigned long long ull;

#define Bb 2048
#define Tt 1000
#define Ii 40
#define Hh 16
#define TS 20
#define NCH (Tt/TS)
#define PADF 8
#define BSTR (TS*Ii + PADF)     /* 808 floats per batch-sub slot (16B aligned) */
#define BUFF (2*BSTR)           /* per-buffer floats (2 batch elems) */
#define CHBYTES (TS*Ii*4)       /* 3200B per batch per chunk */

// -------- device-global scratch (no allocation allowed) --------
__device__ float2 g_wp[32*20];       // per neuron-branch nb=2h+br: 20 weight pairs, pre-scaled (1-a)(1-b)
__device__ float  g_alphah[Hh];      // alpha per neuron
__device__ float  g_betab[32];       // beta per neuron-branch
__device__ float2 g_w2[Hh];          // (W2[0][h], W2[1][h])
__device__ float2 g_b2c;
// spike masks as bytes: [pair][t][bsub][wrp]  (wrp0 = neurons 0-7, wrp1 = neurons 8-15)
__device__ uint8_t g_masks8[(size_t)(Bb/2)*Tt*4];

// -------- packed f32x2 helpers --------
__device__ __forceinline__ ull pk2(float a, float b){ ull r; asm("mov.b64 %0,{%1,%2};":"=l"(r):"f"(a),"f"(b)); return r; }
__device__ __forceinline__ void upk2(ull v, float&a, float&b){ asm("mov.b64 {%0,%1},%2;":"=f"(a),"=f"(b):"l"(v)); }
__device__ __forceinline__ ull fma2(ull a, ull b, ull c){ ull d; asm("fma.rn.f32x2 %0,%1,%2,%3;":"=l"(d):"l"(a),"l"(b),"l"(c)); return d; }
__device__ __forceinline__ ull mul2(ull a, ull b){ ull d; asm("mul.rn.f32x2 %0,%1,%2;":"=l"(d):"l"(a),"l"(b)); return d; }
__device__ __forceinline__ ull add2(ull a, ull b){ ull d; asm("add.rn.f32x2 %0,%1,%2;":"=l"(d):"l"(a),"l"(b)); return d; }
// non-volatile: allow ptxas to schedule loads across steps
__device__ __forceinline__ void lds128(uint32_t a, ull&u, ull&v){ asm("ld.shared.v2.b64 {%0,%1},[%2];":"=l"(u),"=l"(v):"r"(a)); }
__device__ __forceinline__ void stg8_pred(int pred, uint8_t* p, uint32_t v){
  asm volatile("{ .reg .pred q; setp.ne.s32 q,%0,0; @q st.global.b8 [%1],%2; }"
               :: "r"(pred), "l"(p), "r"(v) : "memory");
}
// -------- TMA bulk copy + mbarrier --------
__device__ __forceinline__ void bulkcp(uint32_t dst, const void* src, uint32_t bytes, uint32_t bar){
  asm volatile("cp.async.bulk.shared::cta.global.mbarrier::complete_tx::bytes [%0],[%1],%2,[%3];"
               :: "r"(dst), "l"(src), "r"(bytes), "r"(bar) : "memory");
}
__device__ __forceinline__ void mbar_init(uint32_t bar, uint32_t cnt){
  asm volatile("mbarrier.init.shared.b64 [%0],%1;" :: "r"(bar), "r"(cnt) : "memory");
}
__device__ __forceinline__ void mbar_expect_tx(uint32_t bar, uint32_t bytes){
  asm volatile("mbarrier.arrive.expect_tx.shared.b64 _,[%0],%1;" :: "r"(bar), "r"(bytes) : "memory");
}
__device__ __forceinline__ void mbar_wait(uint32_t bar, uint32_t parity){
  uint32_t done;
  asm volatile("{\n\t.reg .pred p;\n\t"
               "mbarrier.try_wait.parity.acquire.cta.shared::cta.b64 p,[%1],%2;\n\t"
               "selp.b32 %0,1,0,p;\n\t}"
               : "=r"(done) : "r"(bar), "r"(parity) : "memory");
  if (!done){
    asm volatile("{\n\t.reg .pred P1;\n\t"
                 "WL_%=:\n\t"
                 "mbarrier.try_wait.parity.acquire.cta.shared::cta.b64 P1,[%0],%1,0x989680;\n\t"
                 "@P1 bra.uni WD_%=;\n\t"
                 "bra.uni WL_%=;\n\t"
                 "WD_%=:\n\t}"
                 :: "r"(bar), "r"(parity) : "memory");
  }
}

// ---------------- pack: pre-scale weights per neuron-branch + init scalar outputs ----------------
__global__ void pack_kernel(const float* __restrict__ W1, const float* __restrict__ tau_m,
                            const float* __restrict__ tau_n, const float* __restrict__ mask,
                            const float* __restrict__ W2, const float* __restrict__ b2,
                            float* __restrict__ out, long long corrIdx, long long totIdx){
  int tid = threadIdx.x;                    // 640 threads: (nb, k) pairs
  if (tid < 32*20){
    int nb = tid / 20, k = tid % 20;
    int h = nb >> 1;
    float a  = 1.0f/(1.0f + expf(-tau_m[h]));
    float be = 1.0f/(1.0f + expf(-tau_n[nb]));
    float s  = (1.0f - a)*(1.0f - be);      // fold (1-alpha)(1-beta) into weights
    int r = nb*Ii;
    g_wp[tid] = make_float2(W1[r+2*k]*mask[r+2*k]*s, W1[r+2*k+1]*mask[r+2*k+1]*s);
    if (k == 0){
      g_betab[nb] = be;
      if ((nb & 1) == 0){
        g_alphah[h] = a;
        g_w2[h]     = make_float2(W2[h], W2[Hh+h]);
      }
    }
  }
  if (tid == 0){
    g_b2c = make_float2(b2[0], b2[1]);
    out[0] = 0.0f;
    out[corrIdx] = 0.0f;
    int cnt = 0;
    for (int t=0;t<Tt;t++) cnt += ((t>10) && (((t-10)%15)>5)) ? 1 : 0;
    out[totIdx] = (float)cnt * (float)Bb;   // flags.sum() * B
  }
}

// ---------------- main: CTA = 2 batches x 2 warps; warp = 2 batches x 8 neurons x 2 branches ----------
// lane = bsub*16 + br*8 + hloc;  h_global = warp*8 + hloc.  Each lane: one branch's full
// 40-wide dot (10 LDS.128 2-addr broadcast, 20 FFMA2 in 2 chains). Branch sum via
// shfl_xor(d,8); mem duplicated per branch pair. Ballot -> 8-neuron byte per batch,
// 2 predicated STG.8 per warp per step. TMA-staged x shared by both warps.
__global__ void __launch_bounds__(64) snn_kernel(const float* __restrict__ x){
  __shared__ __align__(16) float sx[2*BUFF];
  __shared__ __align__(8) ull smbar[2];
  const int tid  = threadIdx.x;
  const int wrp  = tid >> 5;
  const int lane = tid & 31;
  const int bsub = lane >> 4;
  const int br   = (lane >> 3) & 1;
  const int hloc = lane & 7;
  const int hg   = wrp*8 + hloc;
  const int nb   = 2*hg + br;
  const int b0   = blockIdx.x * 2;

  ull w[20];
  #pragma unroll
  for (int k=0;k<20;k++){ float2 ww = g_wp[nb*20+k]; w[k]=pk2(ww.x,ww.y); }
  const float alpha = g_alphah[hg];
  const float beta  = g_betab[nb];

  float d=0.f, mem=0.f, asel=0.f;
  uint32_t sbase = (uint32_t)__cvta_generic_to_shared(sx);
  uint32_t barb  = (uint32_t)__cvta_generic_to_shared(smbar);

  uint8_t* mrow = g_masks8 + (size_t)blockIdx.x * Tt * 4;
  const int mpred = (lane & 15) == 0;            // lanes 0 and 16 store bytes
  const uint32_t moff = (uint32_t)(bsub*2 + wrp); // byte slot within [t][4]

  const float* xg0 = x + (size_t)b0     * Tt * Ii;
  const float* xg1 = x + (size_t)(b0+1) * Tt * Ii;

  // init barriers + stage chunk 0 (warp 0 lane 0)
  if (tid == 0){
    mbar_init(barb,     1);
    mbar_init(barb + 8, 1);
  }
  __syncthreads();
  if (tid == 0){
    mbar_expect_tx(barb, 2*CHBYTES);
    bulkcp(sbase,            xg0, CHBYTES, barb);
    bulkcp(sbase + BSTR*4u,  xg1, CHBYTES, barb);
  }

  int buf = 0;
  uint32_t pha0 = 0, pha1 = 0;
  for (int c=0;c<NCH;c++){
    __syncthreads();                             // both warps done with buf^1 before refill
    if (tid == 0 && c+1 < NCH){
      uint32_t nbb  = barb + (uint32_t)((buf^1)*8);
      uint32_t sb   = sbase + (uint32_t)((buf^1)*BUFF)*4u;
      mbar_expect_tx(nbb, 2*CHBYTES);
      bulkcp(sb,            xg0 + (size_t)(c+1)*TS*Ii, CHBYTES, nbb);
      bulkcp(sb + BSTR*4u,  xg1 + (size_t)(c+1)*TS*Ii, CHBYTES, nbb);
    }
    if (buf == 0){ mbar_wait(barb,     pha0); pha0 ^= 1; }
    else         { mbar_wait(barb + 8, pha1); pha1 ^= 1; }

    uint32_t xaddr = sbase + (uint32_t)(buf*BUFF + bsub*BSTR)*4u;

    #pragma unroll 4
    for (int tt=0; tt<TS; tt++){
      // dense dot, one branch: 10 LDS.128 (2-addr broadcast) -> 20 pairs, 2 FFMA2 chains
      ull pa, pb;
      lds128(xaddr, pa, pb);
      ull a0 = mul2(w[0], pa), a1 = mul2(w[1], pb);
      #pragma unroll
      for (int j=1;j<10;j++){
        ull xa, xb;
        lds128(xaddr + 16u*j, xa, xb);
        a0 = fma2(w[2*j],   xa, a0);
        a1 = fma2(w[2*j+1], xb, a1);
      }
      float f0,f1;
      ull s = add2(a0,a1); upk2(s,f0,f1);
      float cdot = f0+f1;                       // pre-scaled by (1-a)(1-b)

      // recurrence: branch state local; cross-branch sum via shfl; mem pair-duplicated
      d = fmaf(beta, d, cdot);
      float l = d + __shfl_xor_sync(0xffffffffu, d, 8);
      mem = fmaf(alpha, mem, l) - asel;
      bool sp = mem > 1.0f;
      asel = sp ? alpha : 0.0f;
      uint32_t m = __ballot_sync(0xffffffffu, sp);
      // batch0 byte = bits 0-7 (br0 lanes), batch1 byte = bits 16-23
      uint32_t mv = (lane < 16) ? (m & 0xFFu) : ((m >> 16) & 0xFFu);
      stg8_pred(mpred, mrow + (uint32_t)(c*TS+tt)*4u + moff, mv);

      xaddr += Ii*4;
    }
    buf ^= 1;
  }
}

// ---------------- logits + fast closed-form loss + accuracy ----------------
// thread = one (b,t) point; 16-bit mask = byte pair [pair][t][bsub][0..1].
__global__ void loss_kernel(const int* __restrict__ target, float* __restrict__ out,
                            long long corrIdx){
  __shared__ float2 lut0[256], lut1[256];
  for (int m = threadIdx.x; m < 256; m += blockDim.x){
    float2 a = make_float2(0.f,0.f), b = make_float2(0.f,0.f);
    #pragma unroll
    for (int j=0;j<8;j++){
      if ((m>>j)&1){
        float2 w = g_w2[j];   a.x += w.x; a.y += w.y;
        float2 v = g_w2[8+j]; b.x += v.x; b.y += v.y;
      }
    }
    lut0[m]=a; lut1[m]=b;
  }
  __syncthreads();

  int idx = blockIdx.x * blockDim.x + threadIdx.x;
  float lossv = 0.f, corr = 0.f;
  if (idx < Bb*Tt){
    int b = idx / Tt;
    int t = idx - b*Tt;
    const uint8_t* mp = g_masks8 + ((size_t)(b>>1)*Tt + t)*4 + (b&1)*2;
    uint32_t m16 = *(const uint16_t*)mp;
    float2 lo = lut0[m16 & 0xFF];
    float2 hi = lut1[(m16 >> 8) & 0xFF];
    float2 b2v = g_b2c;
    float z0 = lo.x + hi.x + b2v.x;
    float z1 = lo.y + hi.y + b2v.y;
    out[1 + 2*(size_t)idx]     = z0;
    out[1 + 2*(size_t)idx + 1] = z1;
    if ((t>10) && (((t-10)%15)>5)){
      int tgt = target[idx];
      // closed-form double-softmax CE for 2 classes:
      // q = p1-p0 = (e^s-1)/(e^s+1), s = z1-z0
      // loss = ln2 ± q/2 + q^2/8 - q^4/192 + q^6/2880   (|q|<=1, err<3e-5)
      float s  = z1 - z0;
      float e  = __expf(s);
      float r  = __fdividef(1.0f, 1.0f + e);
      float q  = (e - 1.0f) * r;
      float q2 = q*q;
      float even = 0.6931471805599453f
                 + q2*(0.125f + q2*(-5.208333333e-3f + q2*3.472222222e-4f));
      float lossp = even + ((tgt==0) ? 0.5f : -0.5f) * q;
      lossv = lossp * (1.0f/(float)Bb);
      corr  = ((((s>0.0f)?1:0)==tgt)) ? 1.0f : 0.0f;
    }
  }
  #pragma unroll
  for (int off=16; off; off>>=1){
    lossv += __shfl_xor_sync(0xffffffffu, lossv, off);
    corr  += __shfl_xor_sync(0xffffffffu, corr,  off);
  }
  __shared__ float sl[32], sc[32];
  int wq = threadIdx.x>>5, ln = threadIdx.x&31;
  if (ln==0){ sl[wq]=lossv; sc[wq]=corr; }
  __syncthreads();
  if (wq==0){
    int nw = blockDim.x>>5;
    lossv = (ln<nw)? sl[ln]:0.f;
    corr  = (ln<nw)? sc[ln]:0.f;
    #pragma unroll
    for (int off=4; off; off>>=1){
      lossv += __shfl_xor_sync(0xffffffffu,lossv,off);
      corr  += __shfl_xor_sync(0xffffffffu,corr, off);
    }
    if (ln==0){ atomicAdd(out, lossv); atomicAdd(out+corrIdx, corr); }
  }
}

extern "C" void kernel_launch(void* const* d_in, const int* in_sizes, int n_in,
                              void* d_out, int out_size){
  const float* x      = (const float*)d_in[0];
  const int*   target = (const int*)  d_in[1];
  const float* W1     = (const float*)d_in[2];
  const float* tau_m  = (const float*)d_in[3];
  const float* tau_n  = (const float*)d_in[4];
  const float* mask   = (const float*)d_in[5];
  const float* W2     = (const float*)d_in[6];
  const float* b2     = (const float*)d_in[7];
  float* out = (float*)d_out;
  long long corrIdx = (long long)out_size - 2;   // layout: [loss, logits(B*T*2), correct, total]
  long long totIdx  = (long long)out_size - 1;

  pack_kernel<<<1, 640>>>(W1, tau_m, tau_n, mask, W2, b2, out, corrIdx, totIdx);
  snn_kernel<<<Bb/2, 64>>>(x);
  loss_kernel<<<(Bb*Tt + 255)/256, 256>>>(target, out, corrIdx);
}